// round 2
// baseline (speedup 1.0000x reference)
#include <cuda_runtime.h>
#include <math.h>

// Problem constants
#define BB   2048
#define CC   64
#define DH   512
#define K3   1536
#define SCALE 0.044194173824159216f   // 1/sqrt(512)

typedef unsigned long long u64;

// -------- scratch (static device globals; no allocations) --------
__device__ float g_ctx [BB * K3];   // packed context [B,1536]
__device__ float g_Q   [BB * DH];   // Q = ctx @ Wq^T
__device__ float g_qt  [BB * DH];   // q~ = Q @ Wk
__device__ float g_gbar[BB * DH];   // attn @ G
__device__ float g_gl  [BB * DH];   // glimpse = gbar @ Wv^T
__device__ float g_kt  [BB * DH];   // k~ = glimpse @ Wk
__device__ int   g_dbl_is_u8;       // 1 if `double` buffer is 1-byte, 0 if int32

// -------- f32x2 packed-FMA helpers (sm_103a FFMA2) --------
__device__ __forceinline__ u64 dup_f32(float x) {
    u64 r;
    asm("mov.b64 %0, {%1, %1};" : "=l"(r) : "r"(__float_as_uint(x)));
    return r;
}
__device__ __forceinline__ void fma_f32x2(u64 &d, u64 a, u64 b) {
    asm("fma.rn.f32x2 %0, %1, %2, %0;" : "+l"(d) : "l"(a), "l"(b));
}
__device__ __forceinline__ float2 unpack_f32x2(u64 v) {
    unsigned lo, hi;
    asm("mov.b64 {%0, %1}, %2;" : "=r"(lo), "=r"(hi) : "l"(v));
    float2 r; r.x = __uint_as_float(lo); r.y = __uint_as_float(hi);
    return r;
}

// -------- sniff `double` dtype: uint8 vs int32 --------
// If int32: all byte offsets not divisible by 4 (within first 2048 bytes =
// elements 0..511) are zero. If uint8: odd offsets hold ~1024 random 1s.
__global__ void sniff_dbl_kernel(const unsigned char* __restrict__ p) {
    __shared__ int any;
    if (threadIdx.x == 0) any = 0;
    __syncthreads();
    int found = 0;
    for (int i = threadIdx.x; i < 2048; i += 256)
        if ((i & 3) && p[i]) found = 1;
    if (found) any = 1;
    __syncthreads();
    if (threadIdx.x == 0) g_dbl_is_u8 = any;
}

// -------- pack context = [H_X | Ht_S | Eq_Q] --------
__global__ void pack_ctx_kernel(float4* __restrict__ ctx,
                                const float4* __restrict__ hx,
                                const float4* __restrict__ hs,
                                const float4* __restrict__ eq) {
    int idx = blockIdx.x * blockDim.x + threadIdx.x;   // over BB*384 float4s
    int b = idx / 384;
    int r = idx - b * 384;
    float4 v;
    if (r < 128)       v = hx[b * 128 + r];
    else if (r < 256)  v = hs[b * 128 + (r - 128)];
    else               v = eq[b * 128 + (r - 256)];
    ctx[idx] = v;
}

// -------- fp32 GEMM: C[M,N] = A[M,K] * B --------
// TRANSB=1: W is [N,K] row-major (B(k,n) = W[n*K+k])
// TRANSB=0: W is [K,N] row-major (B(k,n) = W[k*N+n])
// Tile 128x64x16, 256 threads, 8x4 per-thread via f32x2 (pairs over M).
template<int TRANSB>
__global__ void __launch_bounds__(256) gemm_kernel(
    float* __restrict__ C, const float* __restrict__ A,
    const float* __restrict__ W, int M, int N, int K)
{
    const int BM = 128, BN = 64, BK = 16, BMp = BM + 4;
    __shared__ __align__(16) float As[BK * BMp];
    __shared__ __align__(16) float Bs[BK * BN];

    int tid = threadIdx.x;
    int tx = tid & 15;       // 0..15 (N direction, 4 cols each)
    int ty = tid >> 4;       // 0..15 (M direction, 8 rows each)
    int bm = blockIdx.y * BM;
    int bn = blockIdx.x * BN;

    u64 acc[4][4];
    #pragma unroll
    for (int i = 0; i < 4; i++)
        #pragma unroll
        for (int j = 0; j < 4; j++) acc[i][j] = 0ull;

    for (int k0 = 0; k0 < K; k0 += BK) {
        // ---- load A tile (128x16), store transposed As[k][m] ----
        #pragma unroll
        for (int h = 0; h < 2; h++) {
            int v  = tid + h * 256;        // 0..511
            int m  = v >> 2;
            int kq = (v & 3) * 4;
            float4 a4 = *(const float4*)(A + (size_t)(bm + m) * K + k0 + kq);
            As[(kq + 0) * BMp + m] = a4.x;
            As[(kq + 1) * BMp + m] = a4.y;
            As[(kq + 2) * BMp + m] = a4.z;
            As[(kq + 3) * BMp + m] = a4.w;
        }
        // ---- load B tile (16x64) ----
        if (TRANSB) {
            int n  = tid >> 2;             // 0..63
            int kq = (tid & 3) * 4;
            float4 b4 = *(const float4*)(W + (size_t)(bn + n) * K + k0 + kq);
            Bs[(kq + 0) * BN + n] = b4.x;
            Bs[(kq + 1) * BN + n] = b4.y;
            Bs[(kq + 2) * BN + n] = b4.z;
            Bs[(kq + 3) * BN + n] = b4.w;
        } else {
            int k  = tid >> 4;             // 0..15
            int nq = (tid & 15) * 4;
            float4 b4 = *(const float4*)(W + (size_t)(k0 + k) * N + bn + nq);
            *(float4*)(Bs + k * BN + nq) = b4;
        }
        __syncthreads();

        #pragma unroll
        for (int k = 0; k < BK; k++) {
            const float* ap = As + k * BMp + ty * 8;
            u64 a0 = *(const u64*)(ap + 0);
            u64 a1 = *(const u64*)(ap + 2);
            u64 a2 = *(const u64*)(ap + 4);
            u64 a3 = *(const u64*)(ap + 6);
            float4 b4 = *(const float4*)(Bs + k * BN + tx * 4);
            u64 b0 = dup_f32(b4.x), b1 = dup_f32(b4.y),
                b2 = dup_f32(b4.z), b3 = dup_f32(b4.w);
            fma_f32x2(acc[0][0], a0, b0); fma_f32x2(acc[0][1], a0, b1);
            fma_f32x2(acc[0][2], a0, b2); fma_f32x2(acc[0][3], a0, b3);
            fma_f32x2(acc[1][0], a1, b0); fma_f32x2(acc[1][1], a1, b1);
            fma_f32x2(acc[1][2], a1, b2); fma_f32x2(acc[1][3], a1, b3);
            fma_f32x2(acc[2][0], a2, b0); fma_f32x2(acc[2][1], a2, b1);
            fma_f32x2(acc[2][2], a2, b2); fma_f32x2(acc[2][3], a2, b3);
            fma_f32x2(acc[3][0], a3, b0); fma_f32x2(acc[3][1], a3, b1);
            fma_f32x2(acc[3][2], a3, b2); fma_f32x2(acc[3][3], a3, b3);
        }
        __syncthreads();
    }

    // ---- epilogue ----
    #pragma unroll
    for (int i = 0; i < 4; i++) {
        float2 c0 = unpack_f32x2(acc[i][0]);
        float2 c1 = unpack_f32x2(acc[i][1]);
        float2 c2 = unpack_f32x2(acc[i][2]);
        float2 c3 = unpack_f32x2(acc[i][3]);
        int row0 = bm + ty * 8 + 2 * i;
        float4 lo = make_float4(c0.x, c1.x, c2.x, c3.x);
        float4 hi = make_float4(c0.y, c1.y, c2.y, c3.y);
        *(float4*)(C + (size_t)row0 * N + bn + tx * 4)       = lo;
        *(float4*)(C + (size_t)(row0 + 1) * N + bn + tx * 4) = hi;
    }
}

// -------- fused pass 1: logits -> softmax -> gbar (one CTA per batch) --------
__global__ void __launch_bounds__(512) fused1_kernel(
    const float* __restrict__ HtC, const int* __restrict__ caps,
    const int* __restrict__ dists, const float* __restrict__ cemb,
    const float* __restrict__ demb, const float* __restrict__ qt,
    float* __restrict__ gbar)
{
    int b = blockIdx.x, tid = threadIdx.x;
    int w = tid >> 5, l = tid & 31;
    __shared__ __align__(16) float qs[DH];
    __shared__ int   cap_s[CC], dist_s[CC];
    __shared__ float logit_s[CC], attn_s[CC];

    qs[tid] = qt[(size_t)b * DH + tid];
    if (tid < CC) {
        cap_s[tid]  = caps[b * CC + tid];
        dist_s[tid] = dists[b * CC + tid];
    }
    __syncthreads();

    const float4* H4 = (const float4*)HtC + (size_t)b * (CC * DH / 4);
    const float4* q4 = (const float4*)qs;
    #pragma unroll
    for (int r = 0; r < 4; r++) {
        int c = w * 4 + r;
        const float4* hrow = H4 + c * 128;
        const float4* ce = (const float4*)cemb + cap_s[c]  * 128;
        const float4* de = (const float4*)demb + dist_s[c] * 128;
        float acc = 0.f;
        #pragma unroll
        for (int j = 0; j < 4; j++) {
            int i = j * 32 + l;
            float4 h = hrow[i], a = ce[i], d = de[i], q = q4[i];
            acc += (h.x + a.x + d.x) * q.x + (h.y + a.y + d.y) * q.y
                 + (h.z + a.z + d.z) * q.z + (h.w + a.w + d.w) * q.w;
        }
        #pragma unroll
        for (int o = 16; o; o >>= 1) acc += __shfl_xor_sync(0xffffffffu, acc, o);
        if (l == 0) logit_s[c] = acc * SCALE;
    }
    __syncthreads();

    if (w == 0) {
        float x0 = logit_s[l], x1 = logit_s[l + 32];
        float m = fmaxf(x0, x1);
        #pragma unroll
        for (int o = 16; o; o >>= 1) m = fmaxf(m, __shfl_xor_sync(0xffffffffu, m, o));
        float e0 = expf(x0 - m), e1 = expf(x1 - m);
        float s = e0 + e1;
        #pragma unroll
        for (int o = 16; o; o >>= 1) s += __shfl_xor_sync(0xffffffffu, s, o);
        float inv = 1.f / s;
        attn_s[l] = e0 * inv; attn_s[l + 32] = e1 * inv;
    }
    __syncthreads();

    // gbar[d] = sum_c attn[c] * G[c][d]   (re-read hits L1/L2)
    const float* Hb = HtC + (size_t)b * (CC * DH);
    float acc = 0.f;
    #pragma unroll 8
    for (int c = 0; c < CC; c++) {
        float g = Hb[c * DH + tid] + cemb[cap_s[c] * DH + tid]
                + demb[dist_s[c] * DH + tid];
        acc = fmaf(attn_s[c], g, acc);
    }
    gbar[(size_t)b * DH + tid] = acc;
}

// -------- fused pass 2: u -> mask -> softmax -> out --------
__global__ void __launch_bounds__(512) fused2_kernel(
    const float* __restrict__ HtC, const int* __restrict__ caps,
    const int* __restrict__ dists, const float* __restrict__ cemb,
    const float* __restrict__ demb, const float* __restrict__ kt,
    const void* __restrict__ dbl, float* __restrict__ out)
{
    int b = blockIdx.x, tid = threadIdx.x;
    int w = tid >> 5, l = tid & 31;
    __shared__ __align__(16) float ks[DH];
    __shared__ int   cap_s[CC], dist_s[CC];
    __shared__ float u_s[CC];

    ks[tid] = kt[(size_t)b * DH + tid];
    if (tid < CC) {
        cap_s[tid]  = caps[b * CC + tid];
        dist_s[tid] = dists[b * CC + tid];
    }
    __syncthreads();

    // `double` dtype resolved at runtime by sniff kernel (uniform branch)
    int dval = g_dbl_is_u8 ? (int)((const unsigned char*)dbl)[b]
                           : ((const int*)dbl)[b];
    int need = dval ? 2 : 1;

    const float4* H4 = (const float4*)HtC + (size_t)b * (CC * DH / 4);
    const float4* k4 = (const float4*)ks;
    #pragma unroll
    for (int r = 0; r < 4; r++) {
        int c = w * 4 + r;
        const float4* hrow = H4 + c * 128;
        const float4* ce = (const float4*)cemb + cap_s[c]  * 128;
        const float4* de = (const float4*)demb + dist_s[c] * 128;
        float acc = 0.f;
        #pragma unroll
        for (int j = 0; j < 4; j++) {
            int i = j * 32 + l;
            float4 h = hrow[i], a = ce[i], d = de[i], q = k4[i];
            acc += (h.x + a.x + d.x) * q.x + (h.y + a.y + d.y) * q.y
                 + (h.z + a.z + d.z) * q.z + (h.w + a.w + d.w) * q.w;
        }
        #pragma unroll
        for (int o = 16; o; o >>= 1) acc += __shfl_xor_sync(0xffffffffu, acc, o);
        if (l == 0) {
            float uu = acc * SCALE;
            if (cap_s[c] < need) uu = __int_as_float(0xff800000); // -inf
            u_s[c] = uu;
        }
    }
    __syncthreads();

    if (w == 0) {
        float x0 = u_s[l], x1 = u_s[l + 32];
        float m = fmaxf(x0, x1);
        #pragma unroll
        for (int o = 16; o; o >>= 1) m = fmaxf(m, __shfl_xor_sync(0xffffffffu, m, o));
        float e0 = expf(x0 - m), e1 = expf(x1 - m);
        float s = e0 + e1;
        #pragma unroll
        for (int o = 16; o; o >>= 1) s += __shfl_xor_sync(0xffffffffu, s, o);
        float inv = 1.f / s;
        out[(size_t)b * CC + l]      = e0 * inv;
        out[(size_t)b * CC + l + 32] = e1 * inv;
    }
}

extern "C" void kernel_launch(void* const* d_in, const int* in_sizes, int n_in,
                              void* d_out, int out_size) {
    const float* HtC   = (const float*)d_in[0];
    const int*   caps  = (const int*)  d_in[1];
    const int*   dists = (const int*)  d_in[2];
    const float* HX    = (const float*)d_in[3];
    const float* HS    = (const float*)d_in[4];
    const float* EQ    = (const float*)d_in[5];
    const void*  dbl   = d_in[6];
    const float* cemb  = (const float*)d_in[7];
    const float* demb  = (const float*)d_in[8];
    const float* Wq    = (const float*)d_in[9];
    const float* Wk    = (const float*)d_in[10];
    const float* Wv    = (const float*)d_in[11];
    float* out = (float*)d_out;

    float *ctx, *Q, *qt, *gbar, *gl, *kt;
    cudaGetSymbolAddress((void**)&ctx,  g_ctx);
    cudaGetSymbolAddress((void**)&Q,    g_Q);
    cudaGetSymbolAddress((void**)&qt,   g_qt);
    cudaGetSymbolAddress((void**)&gbar, g_gbar);
    cudaGetSymbolAddress((void**)&gl,   g_gl);
    cudaGetSymbolAddress((void**)&kt,   g_kt);

    // 0) sniff dtype of `double`
    sniff_dbl_kernel<<<1, 256>>>((const unsigned char*)dbl);
    // 1) pack context
    pack_ctx_kernel<<<(BB * 384) / 256, 256>>>(
        (float4*)ctx, (const float4*)HX, (const float4*)HS, (const float4*)EQ);

    dim3 gemm_grid(DH / 64, BB / 128);
    // 2) Q = ctx @ Wq^T   (Wq: [512,1536])
    gemm_kernel<1><<<gemm_grid, 256>>>(Q, ctx, Wq, BB, DH, K3);
    // 3) q~ = Q @ Wk      (Wk: [512,512])
    gemm_kernel<0><<<gemm_grid, 256>>>(qt, Q, Wk, BB, DH, DH);
    // 4) logits/softmax/gbar
    fused1_kernel<<<BB, 512>>>(HtC, caps, dists, cemb, demb, qt, gbar);
    // 5) glimpse = gbar @ Wv^T
    gemm_kernel<1><<<gemm_grid, 256>>>(gl, gbar, Wv, BB, DH, DH);
    // 6) k~ = glimpse @ Wk
    gemm_kernel<0><<<gemm_grid, 256>>>(kt, gl, Wk, BB, DH, DH);
    // 7) u/mask/softmax -> out
    fused2_kernel<<<BB, 512>>>(HtC, caps, dists, cemb, demb, kt, dbl, out);
}

// round 4
// speedup vs baseline: 1.4792x; 1.4792x over previous
#include <cuda_runtime.h>
#include <cuda_bf16.h>
#include <math.h>
#include <stdint.h>

// Problem constants
#define BB   2048
#define CC   64
#define DH   512
#define K3   1536
#define SCALE 0.044194173824159216f   // 1/sqrt(512)

typedef unsigned long long u64;
typedef __nv_bfloat16 bf16;

// ---------------- scratch (static device globals) ----------------
__device__ bf16  g_ctx_h [BB * K3];
__device__ bf16  g_ctx_l [BB * K3];
__device__ bf16  g_WqT_h [K3 * DH];   // WqT[i,e] = Wq[e,i]
__device__ bf16  g_WqT_l [K3 * DH];
__device__ bf16  g_WkT_h [DH * DH];
__device__ bf16  g_WkT_l [DH * DH];
__device__ bf16  g_WvT_h [DH * DH];
__device__ bf16  g_WvT_l [DH * DH];
__device__ bf16  g_W1t_h [DH * K3];   // W1t[d,i] = sum_e WkT[d,e]*WqT[i,e]
__device__ bf16  g_W1t_l [DH * K3];
__device__ bf16  g_M2t_h [DH * DH];   // M2t[d,e2] = sum_e WkT[d,e]*WvT[e2,e]
__device__ bf16  g_M2t_l [DH * DH];
__device__ float g_qt    [BB * DH];
__device__ bf16  g_gbar_h[BB * DH];
__device__ bf16  g_gbar_l[BB * DH];
__device__ float g_kt    [BB * DH];
__device__ int   g_dbl_is_u8;

// ---------------- helpers ----------------
__device__ __forceinline__ uint32_t smem_u32(const void* p) {
    uint32_t a;
    asm("{ .reg .u64 t; cvta.to.shared.u64 t, %1; cvt.u32.u64 %0, t; }" : "=r"(a) : "l"(p));
    return a;
}
__device__ __forceinline__ void cp_async16(uint32_t dst, const void* src) {
    asm volatile("cp.async.cg.shared.global [%0], [%1], 16;" :: "r"(dst), "l"(src) : "memory");
}
__device__ __forceinline__ void cp_commit() {
    asm volatile("cp.async.commit_group;" ::: "memory");
}
__device__ __forceinline__ void split_bf16(float f, bf16& h, bf16& l) {
    h = __float2bfloat16_rn(f);
    l = __float2bfloat16_rn(f - __bfloat162float(h));
}
__device__ __forceinline__ void mma_bf16(float* c, const uint32_t* a, const uint32_t* b) {
    asm volatile(
        "mma.sync.aligned.m16n8k16.row.col.f32.bf16.bf16.f32 "
        "{%0,%1,%2,%3}, {%4,%5,%6,%7}, {%8,%9}, {%0,%1,%2,%3};"
        : "+f"(c[0]), "+f"(c[1]), "+f"(c[2]), "+f"(c[3])
        : "r"(a[0]), "r"(a[1]), "r"(a[2]), "r"(a[3]), "r"(b[0]), "r"(b[1]));
}

// ---------------- sniff `double` dtype ----------------
__global__ void sniff_dbl_kernel(const unsigned char* __restrict__ p) {
    __shared__ int any;
    if (threadIdx.x == 0) any = 0;
    __syncthreads();
    int found = 0;
    for (int i = threadIdx.x; i < 2048; i += 256)
        if ((i & 3) && p[i]) found = 1;
    if (found) any = 1;
    __syncthreads();
    if (threadIdx.x == 0) g_dbl_is_u8 = any;
}

// ---------------- pack context + split to bf16 hi/lo ----------------
__global__ void pack_split_kernel(uint2* __restrict__ ch, uint2* __restrict__ cl,
                                  const float4* __restrict__ hx,
                                  const float4* __restrict__ hs,
                                  const float4* __restrict__ eq) {
    int idx = blockIdx.x * blockDim.x + threadIdx.x;   // BB*384 float4s
    int b = idx / 384;
    int r = idx - b * 384;
    float4 v;
    if (r < 128)       v = hx[b * 128 + r];
    else if (r < 256)  v = hs[b * 128 + (r - 128)];
    else               v = eq[b * 128 + (r - 256)];
    bf16 h0,l0,h1,l1,h2,l2,h3,l3;
    split_bf16(v.x,h0,l0); split_bf16(v.y,h1,l1);
    split_bf16(v.z,h2,l2); split_bf16(v.w,h3,l3);
    __nv_bfloat162 H01 = {h0,h1}, H23 = {h2,h3}, L01 = {l0,l1}, L23 = {l2,l3};
    ch[idx] = make_uint2(*(uint32_t*)&H01, *(uint32_t*)&H23);
    cl[idx] = make_uint2(*(uint32_t*)&L01, *(uint32_t*)&L23);
}

// ---------------- transpose fp32 [R,Cn] -> split bf16 [Cn,R] ----------------
__global__ void trans_split_kernel(const float* __restrict__ in,
                                   bf16* __restrict__ oh, bf16* __restrict__ ol,
                                   int R, int Cn) {
    __shared__ float t[32][33];
    int i0 = blockIdx.x * 32, e0 = blockIdx.y * 32;
    int tx = threadIdx.x, ty = threadIdx.y;
    #pragma unroll
    for (int j = 0; j < 32; j += 8)
        t[ty + j][tx] = in[(size_t)(e0 + ty + j) * Cn + i0 + tx];
    __syncthreads();
    #pragma unroll
    for (int j = 0; j < 32; j += 8) {
        float f = t[tx][ty + j];
        bf16 h, l; split_bf16(f, h, l);
        size_t o = (size_t)(i0 + ty + j) * R + e0 + tx;
        oh[o] = h; ol[o] = l;
    }
}

// ---------------- mma.sync GEMM: D[m,n] = sum_k A[m,k]*B[n,k] ----------------
// bf16 hi/lo operands, K-major; 3-term split accumulated in fp32.
// CTA tile 128x64, BK=32, 256 threads (8 warps: 4M x 2N), warp tile 32x32.
// smem rows padded to 80B (conflict-free for fragment LDS pattern).
#define MG_AH   0
#define MG_AL   10240
#define MG_BH   20480
#define MG_BL   25600
#define MG_STG  30720
#define MG_SMEM (2 * MG_STG)

template<int SPLIT_OUT>
__global__ void __launch_bounds__(256, 1) mma_gemm_kernel(
    float* __restrict__ outf, bf16* __restrict__ outh, bf16* __restrict__ outl,
    const bf16* __restrict__ Ah, const bf16* __restrict__ Al,
    const bf16* __restrict__ Bh, const bf16* __restrict__ Bl,
    int N, int K)
{
    extern __shared__ char dsm[];
    uint32_t sb0 = smem_u32(dsm);

    int tid = threadIdx.x;
    int lane = tid & 31, wid = tid >> 5;
    int wm = wid & 3, wn = wid >> 2;          // 4 M-warps x 2 N-warps
    int gid = lane >> 2, tid4 = lane & 3;
    int bm = blockIdx.y * 128, bn = blockIdx.x * 64;
    int KB = K >> 5;

    float C[2][4][4];
    #pragma unroll
    for (int t = 0; t < 2; t++)
        #pragma unroll
        for (int j = 0; j < 4; j++)
            #pragma unroll
            for (int q = 0; q < 4; q++) C[t][j][q] = 0.f;

    auto load_stage = [&](int kb, int s) {
        uint32_t sb = sb0 + s * MG_STG;
        int ko = kb * 32;
        // i=0,1: A_h (512 x 16B), i=2,3: A_l, i=4: B_h (256), i=5: B_l
        #pragma unroll
        for (int i = 0; i < 6; i++) {
            int v = tid + i * 256;
            if (v < 512) {
                int r = v >> 2, c = v & 3;
                cp_async16(sb + MG_AH + r * 80 + c * 16,
                           Ah + (size_t)(bm + r) * K + ko + c * 8);
            } else if (v < 1024) {
                int u = v - 512; int r = u >> 2, c = u & 3;
                cp_async16(sb + MG_AL + r * 80 + c * 16,
                           Al + (size_t)(bm + r) * K + ko + c * 8);
            } else if (v < 1280) {
                int u = v - 1024; int r = u >> 2, c = u & 3;
                cp_async16(sb + MG_BH + r * 80 + c * 16,
                           Bh + (size_t)(bn + r) * K + ko + c * 8);
            } else {
                int u = v - 1280; int r = u >> 2, c = u & 3;
                cp_async16(sb + MG_BL + r * 80 + c * 16,
                           Bl + (size_t)(bn + r) * K + ko + c * 8);
            }
        }
        cp_commit();
    };

    load_stage(0, 0);

    for (int kb = 0; kb < KB; kb++) {
        if (kb + 1 < KB) {
            load_stage(kb + 1, (kb + 1) & 1);
            asm volatile("cp.async.wait_group 1;" ::: "memory");
        } else {
            asm volatile("cp.async.wait_group 0;" ::: "memory");
        }
        __syncthreads();

        const char* st = dsm + (kb & 1) * MG_STG;
        #pragma unroll
        for (int step = 0; step < 2; step++) {
            int k = step * 16 + tid4 * 2;
            uint32_t ah[2][4], al[2][4], bh[4][2], bl[4][2];
            #pragma unroll
            for (int t = 0; t < 2; t++) {
                int r = wm * 32 + t * 16 + gid;
                ah[t][0] = *(const uint32_t*)(st + MG_AH + r * 80 + k * 2);
                ah[t][1] = *(const uint32_t*)(st + MG_AH + (r + 8) * 80 + k * 2);
                ah[t][2] = *(const uint32_t*)(st + MG_AH + r * 80 + (k + 8) * 2);
                ah[t][3] = *(const uint32_t*)(st + MG_AH + (r + 8) * 80 + (k + 8) * 2);
                al[t][0] = *(const uint32_t*)(st + MG_AL + r * 80 + k * 2);
                al[t][1] = *(const uint32_t*)(st + MG_AL + (r + 8) * 80 + k * 2);
                al[t][2] = *(const uint32_t*)(st + MG_AL + r * 80 + (k + 8) * 2);
                al[t][3] = *(const uint32_t*)(st + MG_AL + (r + 8) * 80 + (k + 8) * 2);
            }
            #pragma unroll
            for (int j = 0; j < 4; j++) {
                int n = wn * 32 + j * 8 + gid;
                bh[j][0] = *(const uint32_t*)(st + MG_BH + n * 80 + k * 2);
                bh[j][1] = *(const uint32_t*)(st + MG_BH + n * 80 + (k + 8) * 2);
                bl[j][0] = *(const uint32_t*)(st + MG_BL + n * 80 + k * 2);
                bl[j][1] = *(const uint32_t*)(st + MG_BL + n * 80 + (k + 8) * 2);
            }
            #pragma unroll
            for (int t = 0; t < 2; t++)
                #pragma unroll
                for (int j = 0; j < 4; j++) {
                    mma_bf16(C[t][j], ah[t], bh[j]);
                    mma_bf16(C[t][j], ah[t], bl[j]);
                    mma_bf16(C[t][j], al[t], bh[j]);
                }
        }
        __syncthreads();
    }

    // epilogue
    #pragma unroll
    for (int t = 0; t < 2; t++) {
        int m0 = bm + wm * 32 + t * 16 + gid;
        #pragma unroll
        for (int j = 0; j < 4; j++) {
            int col = bn + wn * 32 + j * 8 + tid4 * 2;
            if (SPLIT_OUT) {
                bf16 h0,l0,h1,l1;
                split_bf16(C[t][j][0], h0, l0); split_bf16(C[t][j][1], h1, l1);
                __nv_bfloat162 H = {h0,h1}, L = {l0,l1};
                *(uint32_t*)(outh + (size_t)m0 * N + col) = *(uint32_t*)&H;
                *(uint32_t*)(outl + (size_t)m0 * N + col) = *(uint32_t*)&L;
                split_bf16(C[t][j][2], h0, l0); split_bf16(C[t][j][3], h1, l1);
                __nv_bfloat162 H2 = {h0,h1}, L2 = {l0,l1};
                *(uint32_t*)(outh + (size_t)(m0 + 8) * N + col) = *(uint32_t*)&H2;
                *(uint32_t*)(outl + (size_t)(m0 + 8) * N + col) = *(uint32_t*)&L2;
            } else {
                *(float2*)(outf + (size_t)m0 * N + col)       = make_float2(C[t][j][0], C[t][j][1]);
                *(float2*)(outf + (size_t)(m0 + 8) * N + col) = make_float2(C[t][j][2], C[t][j][3]);
            }
        }
    }
}

// ---------------- fused pass 1: logits -> softmax -> gbar(split) ----------------
__global__ void __launch_bounds__(512) fused1_kernel(
    const float* __restrict__ HtC, const int* __restrict__ caps,
    const int* __restrict__ dists, const float* __restrict__ cemb,
    const float* __restrict__ demb, const float* __restrict__ qt,
    bf16* __restrict__ gbh, bf16* __restrict__ gbl)
{
    int b = blockIdx.x, tid = threadIdx.x;
    int w = tid >> 5, l = tid & 31;
    __shared__ __align__(16) float qs[DH];
    __shared__ int   cap_s[CC], dist_s[CC];
    __shared__ float logit_s[CC], attn_s[CC];

    qs[tid] = qt[(size_t)b * DH + tid];
    if (tid < CC) {
        cap_s[tid]  = caps[b * CC + tid];
        dist_s[tid] = dists[b * CC + tid];
    }
    __syncthreads();

    const float4* H4 = (const float4*)HtC + (size_t)b * (CC * DH / 4);
    const float4* q4 = (const float4*)qs;
    #pragma unroll
    for (int r = 0; r < 4; r++) {
        int c = w * 4 + r;
        const float4* hrow = H4 + c * 128;
        const float4* ce = (const float4*)cemb + cap_s[c]  * 128;
        const float4* de = (const float4*)demb + dist_s[c] * 128;
        float acc = 0.f;
        #pragma unroll
        for (int j = 0; j < 4; j++) {
            int i = j * 32 + l;
            float4 h = hrow[i], a = ce[i], d = de[i], q = q4[i];
            acc += (h.x + a.x + d.x) * q.x + (h.y + a.y + d.y) * q.y
                 + (h.z + a.z + d.z) * q.z + (h.w + a.w + d.w) * q.w;
        }
        #pragma unroll
        for (int o = 16; o; o >>= 1) acc += __shfl_xor_sync(0xffffffffu, acc, o);
        if (l == 0) logit_s[c] = acc * SCALE;
    }
    __syncthreads();

    if (w == 0) {
        float x0 = logit_s[l], x1 = logit_s[l + 32];
        float m = fmaxf(x0, x1);
        #pragma unroll
        for (int o = 16; o; o >>= 1) m = fmaxf(m, __shfl_xor_sync(0xffffffffu, m, o));
        float e0 = expf(x0 - m), e1 = expf(x1 - m);
        float s = e0 + e1;
        #pragma unroll
        for (int o = 16; o; o >>= 1) s += __shfl_xor_sync(0xffffffffu, s, o);
        float inv = 1.f / s;
        attn_s[l] = e0 * inv; attn_s[l + 32] = e1 * inv;
    }
    __syncthreads();

    const float* Hb = HtC + (size_t)b * (CC * DH);
    float acc = 0.f;
    #pragma unroll 8
    for (int c = 0; c < CC; c++) {
        float g = Hb[c * DH + tid] + cemb[cap_s[c] * DH + tid]
                + demb[dist_s[c] * DH + tid];
        acc = fmaf(attn_s[c], g, acc);
    }
    bf16 h, lo; split_bf16(acc, h, lo);
    gbh[(size_t)b * DH + tid] = h;
    gbl[(size_t)b * DH + tid] = lo;
}

// ---------------- fused pass 2: u -> mask -> softmax -> out ----------------
__global__ void __launch_bounds__(512) fused2_kernel(
    const float* __restrict__ HtC, const int* __restrict__ caps,
    const int* __restrict__ dists, const float* __restrict__ cemb,
    const float* __restrict__ demb, const float* __restrict__ kt,
    const void* __restrict__ dbl, float* __restrict__ out)
{
    int b = blockIdx.x, tid = threadIdx.x;
    int w = tid >> 5, l = tid & 31;
    __shared__ __align__(16) float ks[DH];
    __shared__ int   cap_s[CC], dist_s[CC];
    __shared__ float u_s[CC];

    ks[tid] = kt[(size_t)b * DH + tid];
    if (tid < CC) {
        cap_s[tid]  = caps[b * CC + tid];
        dist_s[tid] = dists[b * CC + tid];
    }
    __syncthreads();

    int dval = g_dbl_is_u8 ? (int)((const unsigned char*)dbl)[b]
                           : ((const int*)dbl)[b];
    int need = dval ? 2 : 1;

    const float4* H4 = (const float4*)HtC + (size_t)b * (CC * DH / 4);
    const float4* k4 = (const float4*)ks;
    #pragma unroll
    for (int r = 0; r < 4; r++) {
        int c = w * 4 + r;
        const float4* hrow = H4 + c * 128;
        const float4* ce = (const float4*)cemb + cap_s[c]  * 128;
        const float4* de = (const float4*)demb + dist_s[c] * 128;
        float acc = 0.f;
        #pragma unroll
        for (int j = 0; j < 4; j++) {
            int i = j * 32 + l;
            float4 h = hrow[i], a = ce[i], d = de[i], q = k4[i];
            acc += (h.x + a.x + d.x) * q.x + (h.y + a.y + d.y) * q.y
                 + (h.z + a.z + d.z) * q.z + (h.w + a.w + d.w) * q.w;
        }
        #pragma unroll
        for (int o = 16; o; o >>= 1) acc += __shfl_xor_sync(0xffffffffu, acc, o);
        if (l == 0) {
            float uu = acc * SCALE;
            if (cap_s[c] < need) uu = __int_as_float(0xff800000); // -inf
            u_s[c] = uu;
        }
    }
    __syncthreads();

    if (w == 0) {
        float x0 = u_s[l], x1 = u_s[l + 32];
        float m = fmaxf(x0, x1);
        #pragma unroll
        for (int o = 16; o; o >>= 1) m = fmaxf(m, __shfl_xor_sync(0xffffffffu, m, o));
        float e0 = expf(x0 - m), e1 = expf(x1 - m);
        float s = e0 + e1;
        #pragma unroll
        for (int o = 16; o; o >>= 1) s += __shfl_xor_sync(0xffffffffu, s, o);
        float inv = 1.f / s;
        out[(size_t)b * CC + l]      = e0 * inv;
        out[(size_t)b * CC + l + 32] = e1 * inv;
    }
}

extern "C" void kernel_launch(void* const* d_in, const int* in_sizes, int n_in,
                              void* d_out, int out_size) {
    const float* HtC   = (const float*)d_in[0];
    const int*   caps  = (const int*)  d_in[1];
    const int*   dists = (const int*)  d_in[2];
    const float* HX    = (const float*)d_in[3];
    const float* HS    = (const float*)d_in[4];
    const float* EQ    = (const float*)d_in[5];
    const void*  dbl   = d_in[6];
    const float* cemb  = (const float*)d_in[7];
    const float* demb  = (const float*)d_in[8];
    const float* Wq    = (const float*)d_in[9];
    const float* Wk    = (const float*)d_in[10];
    const float* Wv    = (const float*)d_in[11];
    float* out = (float*)d_out;

    bf16 *ctxh,*ctxl,*wqh,*wql,*wkh,*wkl,*wvh,*wvl,*w1h,*w1l,*m2h,*m2l,*gbh,*gbl;
    float *qt,*kt;
    cudaGetSymbolAddress((void**)&ctxh, g_ctx_h);  cudaGetSymbolAddress((void**)&ctxl, g_ctx_l);
    cudaGetSymbolAddress((void**)&wqh,  g_WqT_h);  cudaGetSymbolAddress((void**)&wql,  g_WqT_l);
    cudaGetSymbolAddress((void**)&wkh,  g_WkT_h);  cudaGetSymbolAddress((void**)&wkl,  g_WkT_l);
    cudaGetSymbolAddress((void**)&wvh,  g_WvT_h);  cudaGetSymbolAddress((void**)&wvl,  g_WvT_l);
    cudaGetSymbolAddress((void**)&w1h,  g_W1t_h);  cudaGetSymbolAddress((void**)&w1l,  g_W1t_l);
    cudaGetSymbolAddress((void**)&m2h,  g_M2t_h);  cudaGetSymbolAddress((void**)&m2l,  g_M2t_l);
    cudaGetSymbolAddress((void**)&gbh,  g_gbar_h); cudaGetSymbolAddress((void**)&gbl,  g_gbar_l);
    cudaGetSymbolAddress((void**)&qt,   g_qt);     cudaGetSymbolAddress((void**)&kt,   g_kt);

    cudaFuncSetAttribute(mma_gemm_kernel<0>, cudaFuncAttributeMaxDynamicSharedMemorySize, MG_SMEM);
    cudaFuncSetAttribute(mma_gemm_kernel<1>, cudaFuncAttributeMaxDynamicSharedMemorySize, MG_SMEM);

    // 0) dtype sniff
    sniff_dbl_kernel<<<1, 256>>>((const unsigned char*)dbl);
    // 1) weight transposes + splits
    trans_split_kernel<<<dim3(K3/32, DH/32), dim3(32,8)>>>(Wq, wqh, wql, DH, K3);
    trans_split_kernel<<<dim3(DH/32, DH/32), dim3(32,8)>>>(Wk, wkh, wkl, DH, DH);
    trans_split_kernel<<<dim3(DH/32, DH/32), dim3(32,8)>>>(Wv, wvh, wvl, DH, DH);
    // 2) pack + split context
    pack_split_kernel<<<(BB*384)/256, 256>>>((uint2*)ctxh, (uint2*)ctxl,
        (const float4*)HX, (const float4*)HS, (const float4*)EQ);
    // 3) W1t[d,i] = sum_e WkT[d,e]*WqT[i,e]   (M=512, N=1536, K=512)
    mma_gemm_kernel<1><<<dim3(K3/64, DH/128), 256, MG_SMEM>>>(
        nullptr, w1h, w1l, wkh, wkl, wqh, wql, K3, DH);
    // 4) M2t[d,e2] = sum_e WkT[d,e]*WvT[e2,e] (M=512, N=512, K=512)
    mma_gemm_kernel<1><<<dim3(DH/64, DH/128), 256, MG_SMEM>>>(
        nullptr, m2h, m2l, wkh, wkl, wvh, wvl, DH, DH);
    // 5) qt[b,d] = sum_i ctx[b,i]*W1t[d,i]    (M=2048, N=512, K=1536)
    mma_gemm_kernel<0><<<dim3(DH/64, BB/128), 256, MG_SMEM>>>(
        qt, nullptr, nullptr, ctxh, ctxl, w1h, w1l, DH, K3);
    // 6) logits/softmax/gbar (split)
    fused1_kernel<<<BB, 512>>>(HtC, caps, dists, cemb, demb, qt, gbh, gbl);
    // 7) kt[b,d] = sum_e2 gbar[b,e2]*M2t[d,e2] (M=2048, N=512, K=512)
    mma_gemm_kernel<0><<<dim3(DH/64, BB/128), 256, MG_SMEM>>>(
        kt, nullptr, nullptr, gbh, gbl, m2h, m2l, DH, DH);
    // 8) u/mask/softmax -> out
    fused2_kernel<<<BB, 512>>>(HtC, caps, dists, cemb, demb, kt, dbl, out);
}

// round 5
// speedup vs baseline: 1.8369x; 1.2418x over previous
#include <cuda_runtime.h>
#include <cuda_bf16.h>
#include <math.h>
#include <stdint.h>

// Problem constants
#define BB   2048
#define CC   64
#define DH   512
#define K3   1536
#define SCALE 0.044194173824159216f   // 1/sqrt(512)

typedef unsigned long long u64;
typedef __nv_bfloat16 bf16;

// ---------------- scratch (static device globals) ----------------
__device__ bf16  g_ctx_h [BB * K3];
__device__ bf16  g_ctx_l [BB * K3];
__device__ bf16  g_WqT_h [K3 * DH];   // WqT[i,e] = Wq[e,i]
__device__ bf16  g_WqT_l [K3 * DH];
__device__ bf16  g_WkT_h [DH * DH];
__device__ bf16  g_WkT_l [DH * DH];
__device__ bf16  g_WvT_h [DH * DH];
__device__ bf16  g_WvT_l [DH * DH];
__device__ bf16  g_W1t_h [DH * K3];   // W1t[d,i] = sum_e WkT[d,e]*WqT[i,e]
__device__ bf16  g_W1t_l [DH * K3];
__device__ bf16  g_M2t_h [DH * DH];   // M2t[d,e2] = sum_e WkT[d,e]*WvT[e2,e]
__device__ bf16  g_M2t_l [DH * DH];
__device__ float g_qt    [BB * DH];
__device__ bf16  g_gbar_h[BB * DH];
__device__ bf16  g_gbar_l[BB * DH];
__device__ float g_kt    [BB * DH];
__device__ int   g_dbl_is_u8;

// ---------------- helpers ----------------
__device__ __forceinline__ uint32_t smem_u32(const void* p) {
    uint32_t a;
    asm("{ .reg .u64 t; cvta.to.shared.u64 t, %1; cvt.u32.u64 %0, t; }" : "=r"(a) : "l"(p));
    return a;
}
__device__ __forceinline__ void cp_async16(uint32_t dst, const void* src) {
    asm volatile("cp.async.cg.shared.global [%0], [%1], 16;" :: "r"(dst), "l"(src) : "memory");
}
__device__ __forceinline__ void cp_commit() {
    asm volatile("cp.async.commit_group;" ::: "memory");
}
__device__ __forceinline__ void split_bf16(float f, bf16& h, bf16& l) {
    h = __float2bfloat16_rn(f);
    l = __float2bfloat16_rn(f - __bfloat162float(h));
}
__device__ __forceinline__ void mma_bf16(float* c, const uint32_t* a, const uint32_t* b) {
    asm volatile(
        "mma.sync.aligned.m16n8k16.row.col.f32.bf16.bf16.f32 "
        "{%0,%1,%2,%3}, {%4,%5,%6,%7}, {%8,%9}, {%0,%1,%2,%3};"
        : "+f"(c[0]), "+f"(c[1]), "+f"(c[2]), "+f"(c[3])
        : "r"(a[0]), "r"(a[1]), "r"(a[2]), "r"(a[3]), "r"(b[0]), "r"(b[1]));
}

// ---------------- prep: 3 weight transposes+splits, plus dtype sniff ----------------
// blocks 0..767: Wq tiles; 768..1023: Wk; 1024..1279: Wv; 1280: sniff.
__global__ void prep_kernel(const float* __restrict__ Wq,
                            const float* __restrict__ Wk,
                            const float* __restrict__ Wv,
                            bf16* __restrict__ wqh, bf16* __restrict__ wql,
                            bf16* __restrict__ wkh, bf16* __restrict__ wkl,
                            bf16* __restrict__ wvh, bf16* __restrict__ wvl,
                            const unsigned char* __restrict__ dblp) {
    int bid = blockIdx.x;
    int tx = threadIdx.x & 31, ty = threadIdx.x >> 5;   // 32 x 8
    if (bid == 1280) {
        __shared__ int any;
        if (threadIdx.x == 0) any = 0;
        __syncthreads();
        int found = 0;
        for (int i = threadIdx.x; i < 2048; i += 256)
            if ((i & 3) && dblp[i]) found = 1;
        if (found) any = 1;
        __syncthreads();
        if (threadIdx.x == 0) g_dbl_is_u8 = any;
        return;
    }
    const float* in; bf16 *oh, *ol; int Cn, bx, by;
    if (bid < 768)       { in = Wq; oh = wqh; ol = wql; Cn = K3; bx = bid % 48;          by = bid / 48; }
    else if (bid < 1024) { in = Wk; oh = wkh; ol = wkl; Cn = DH; bx = (bid - 768) & 15;  by = (bid - 768) >> 4; }
    else                 { in = Wv; oh = wvh; ol = wvl; Cn = DH; bx = (bid - 1024) & 15; by = (bid - 1024) >> 4; }
    __shared__ float t[32][33];
    int i0 = bx * 32, e0 = by * 32;
    #pragma unroll
    for (int j = 0; j < 32; j += 8)
        t[ty + j][tx] = in[(size_t)(e0 + ty + j) * Cn + i0 + tx];
    __syncthreads();
    #pragma unroll
    for (int j = 0; j < 32; j += 8) {
        float f = t[tx][ty + j];
        bf16 h, l; split_bf16(f, h, l);
        size_t o = (size_t)(i0 + ty + j) * DH + e0 + tx;
        oh[o] = h; ol[o] = l;
    }
}

// ---------------- pack context + split to bf16 hi/lo ----------------
__global__ void pack_split_kernel(uint2* __restrict__ ch, uint2* __restrict__ cl,
                                  const float4* __restrict__ hx,
                                  const float4* __restrict__ hs,
                                  const float4* __restrict__ eq) {
    int idx = blockIdx.x * blockDim.x + threadIdx.x;   // BB*384 float4s
    int b = idx / 384;
    int r = idx - b * 384;
    float4 v;
    if (r < 128)       v = hx[b * 128 + r];
    else if (r < 256)  v = hs[b * 128 + (r - 128)];
    else               v = eq[b * 128 + (r - 256)];
    bf16 h0,l0,h1,l1,h2,l2,h3,l3;
    split_bf16(v.x,h0,l0); split_bf16(v.y,h1,l1);
    split_bf16(v.z,h2,l2); split_bf16(v.w,h3,l3);
    __nv_bfloat162 H01 = {h0,h1}, H23 = {h2,h3}, L01 = {l0,l1}, L23 = {l2,l3};
    ch[idx] = make_uint2(*(uint32_t*)&H01, *(uint32_t*)&H23);
    cl[idx] = make_uint2(*(uint32_t*)&L01, *(uint32_t*)&L23);
}

// ---------------- mma.sync GEMM: D[m,n] = sum_k A[m,k]*B[n,k] ----------------
// bf16 hi/lo operands, K-major; 3-term split accumulated in fp32.
// CTA tile 128x64, BK=32, 256 threads (8 warps: 4M x 2N), warp tile 32x32.
#define MG_AH   0
#define MG_AL   10240
#define MG_BH   20480
#define MG_BL   25600
#define MG_STG  30720
#define MG_SMEM (2 * MG_STG)

template<int SPLIT_OUT>
__global__ void __launch_bounds__(256, 1) mma_gemm_kernel(
    float* __restrict__ outf, bf16* __restrict__ outh, bf16* __restrict__ outl,
    const bf16* __restrict__ Ah, const bf16* __restrict__ Al,
    const bf16* __restrict__ Bh, const bf16* __restrict__ Bl,
    int N, int K)
{
    extern __shared__ char dsm[];
    uint32_t sb0 = smem_u32(dsm);

    int tid = threadIdx.x;
    int lane = tid & 31, wid = tid >> 5;
    int wm = wid & 3, wn = wid >> 2;          // 4 M-warps x 2 N-warps
    int gid = lane >> 2, tid4 = lane & 3;
    int bm = blockIdx.y * 128, bn = blockIdx.x * 64;
    int KB = K >> 5;

    float C[2][4][4];
    #pragma unroll
    for (int t = 0; t < 2; t++)
        #pragma unroll
        for (int j = 0; j < 4; j++)
            #pragma unroll
            for (int q = 0; q < 4; q++) C[t][j][q] = 0.f;

    auto load_stage = [&](int kb, int s) {
        uint32_t sb = sb0 + s * MG_STG;
        int ko = kb * 32;
        #pragma unroll
        for (int i = 0; i < 6; i++) {
            int v = tid + i * 256;
            if (v < 512) {
                int r = v >> 2, c = v & 3;
                cp_async16(sb + MG_AH + r * 80 + c * 16,
                           Ah + (size_t)(bm + r) * K + ko + c * 8);
            } else if (v < 1024) {
                int u = v - 512; int r = u >> 2, c = u & 3;
                cp_async16(sb + MG_AL + r * 80 + c * 16,
                           Al + (size_t)(bm + r) * K + ko + c * 8);
            } else if (v < 1280) {
                int u = v - 1024; int r = u >> 2, c = u & 3;
                cp_async16(sb + MG_BH + r * 80 + c * 16,
                           Bh + (size_t)(bn + r) * K + ko + c * 8);
            } else {
                int u = v - 1280; int r = u >> 2, c = u & 3;
                cp_async16(sb + MG_BL + r * 80 + c * 16,
                           Bl + (size_t)(bn + r) * K + ko + c * 8);
            }
        }
        cp_commit();
    };

    load_stage(0, 0);

    for (int kb = 0; kb < KB; kb++) {
        if (kb + 1 < KB) {
            load_stage(kb + 1, (kb + 1) & 1);
            asm volatile("cp.async.wait_group 1;" ::: "memory");
        } else {
            asm volatile("cp.async.wait_group 0;" ::: "memory");
        }
        __syncthreads();

        const char* st = dsm + (kb & 1) * MG_STG;
        #pragma unroll
        for (int step = 0; step < 2; step++) {
            int k = step * 16 + tid4 * 2;
            uint32_t ah[2][4], al[2][4], bh[4][2], bl[4][2];
            #pragma unroll
            for (int t = 0; t < 2; t++) {
                int r = wm * 32 + t * 16 + gid;
                ah[t][0] = *(const uint32_t*)(st + MG_AH + r * 80 + k * 2);
                ah[t][1] = *(const uint32_t*)(st + MG_AH + (r + 8) * 80 + k * 2);
                ah[t][2] = *(const uint32_t*)(st + MG_AH + r * 80 + (k + 8) * 2);
                ah[t][3] = *(const uint32_t*)(st + MG_AH + (r + 8) * 80 + (k + 8) * 2);
                al[t][0] = *(const uint32_t*)(st + MG_AL + r * 80 + k * 2);
                al[t][1] = *(const uint32_t*)(st + MG_AL + (r + 8) * 80 + k * 2);
                al[t][2] = *(const uint32_t*)(st + MG_AL + r * 80 + (k + 8) * 2);
                al[t][3] = *(const uint32_t*)(st + MG_AL + (r + 8) * 80 + (k + 8) * 2);
            }
            #pragma unroll
            for (int j = 0; j < 4; j++) {
                int n = wn * 32 + j * 8 + gid;
                bh[j][0] = *(const uint32_t*)(st + MG_BH + n * 80 + k * 2);
                bh[j][1] = *(const uint32_t*)(st + MG_BH + n * 80 + (k + 8) * 2);
                bl[j][0] = *(const uint32_t*)(st + MG_BL + n * 80 + k * 2);
                bl[j][1] = *(const uint32_t*)(st + MG_BL + n * 80 + (k + 8) * 2);
            }
            #pragma unroll
            for (int t = 0; t < 2; t++)
                #pragma unroll
                for (int j = 0; j < 4; j++) {
                    mma_bf16(C[t][j], ah[t], bh[j]);
                    mma_bf16(C[t][j], ah[t], bl[j]);
                    mma_bf16(C[t][j], al[t], bh[j]);
                }
        }
        __syncthreads();
    }

    // epilogue
    #pragma unroll
    for (int t = 0; t < 2; t++) {
        int m0 = bm + wm * 32 + t * 16 + gid;
        #pragma unroll
        for (int j = 0; j < 4; j++) {
            int col = bn + wn * 32 + j * 8 + tid4 * 2;
            if (SPLIT_OUT) {
                bf16 h0,l0,h1,l1;
                split_bf16(C[t][j][0], h0, l0); split_bf16(C[t][j][1], h1, l1);
                __nv_bfloat162 H = {h0,h1}, L = {l0,l1};
                *(uint32_t*)(outh + (size_t)m0 * N + col) = *(uint32_t*)&H;
                *(uint32_t*)(outl + (size_t)m0 * N + col) = *(uint32_t*)&L;
                split_bf16(C[t][j][2], h0, l0); split_bf16(C[t][j][3], h1, l1);
                __nv_bfloat162 H2 = {h0,h1}, L2 = {l0,l1};
                *(uint32_t*)(outh + (size_t)(m0 + 8) * N + col) = *(uint32_t*)&H2;
                *(uint32_t*)(outl + (size_t)(m0 + 8) * N + col) = *(uint32_t*)&L2;
            } else {
                *(float2*)(outf + (size_t)m0 * N + col)       = make_float2(C[t][j][0], C[t][j][1]);
                *(float2*)(outf + (size_t)(m0 + 8) * N + col) = make_float2(C[t][j][2], C[t][j][3]);
            }
        }
    }
}

// ---------------- fused pass 1: logits -> softmax -> gbar(split) ----------------
// G tile (64x512 fp32 = 128 KB) cached in dynamic smem: Ht_C read ONCE from DRAM.
__global__ void __launch_bounds__(512, 1) fused1_kernel(
    const float* __restrict__ HtC, const int* __restrict__ caps,
    const int* __restrict__ dists, const float* __restrict__ cemb,
    const float* __restrict__ demb, const float* __restrict__ qt,
    bf16* __restrict__ gbh, bf16* __restrict__ gbl)
{
    extern __shared__ float4 gsm4[];   // [CC * 128] float4 = 128 KB
    int b = blockIdx.x, tid = threadIdx.x;
    int w = tid >> 5, l = tid & 31;
    __shared__ __align__(16) float qs[DH];
    __shared__ int   cap_s[CC], dist_s[CC];
    __shared__ float logit_s[CC], attn_s[CC];

    qs[tid] = qt[(size_t)b * DH + tid];
    if (tid < CC) {
        cap_s[tid]  = caps[b * CC + tid];
        dist_s[tid] = dists[b * CC + tid];
    }
    __syncthreads();

    const float4* H4 = (const float4*)HtC + (size_t)b * (CC * DH / 4);
    const float4* q4 = (const float4*)qs;
    #pragma unroll
    for (int r = 0; r < 4; r++) {
        int c = w * 4 + r;
        const float4* hrow = H4 + c * 128;
        const float4* ce = (const float4*)cemb + cap_s[c]  * 128;
        const float4* de = (const float4*)demb + dist_s[c] * 128;
        float acc = 0.f;
        #pragma unroll
        for (int j = 0; j < 4; j++) {
            int i = j * 32 + l;
            float4 h = __ldcs(hrow + i);
            float4 a = ce[i], d = de[i], q = q4[i];
            float4 g = make_float4(h.x + a.x + d.x, h.y + a.y + d.y,
                                   h.z + a.z + d.z, h.w + a.w + d.w);
            gsm4[c * 128 + i] = g;
            acc += g.x * q.x + g.y * q.y + g.z * q.z + g.w * q.w;
        }
        #pragma unroll
        for (int o = 16; o; o >>= 1) acc += __shfl_xor_sync(0xffffffffu, acc, o);
        if (l == 0) logit_s[c] = acc * SCALE;
    }
    __syncthreads();

    if (w == 0) {
        float x0 = logit_s[l], x1 = logit_s[l + 32];
        float m = fmaxf(x0, x1);
        #pragma unroll
        for (int o = 16; o; o >>= 1) m = fmaxf(m, __shfl_xor_sync(0xffffffffu, m, o));
        float e0 = expf(x0 - m), e1 = expf(x1 - m);
        float s = e0 + e1;
        #pragma unroll
        for (int o = 16; o; o >>= 1) s += __shfl_xor_sync(0xffffffffu, s, o);
        float inv = 1.f / s;
        attn_s[l] = e0 * inv; attn_s[l + 32] = e1 * inv;
    }
    __syncthreads();

    // gbar[d] = sum_c attn[c] * G[c][d]  (G from smem)
    const float* gs = (const float*)gsm4;
    float acc = 0.f;
    #pragma unroll 16
    for (int c = 0; c < CC; c++)
        acc = fmaf(attn_s[c], gs[c * DH + tid], acc);
    bf16 h, lo; split_bf16(acc, h, lo);
    gbh[(size_t)b * DH + tid] = h;
    gbl[(size_t)b * DH + tid] = lo;
}

// ---------------- fused pass 2: u -> mask -> softmax -> out ----------------
__global__ void __launch_bounds__(512) fused2_kernel(
    const float* __restrict__ HtC, const int* __restrict__ caps,
    const int* __restrict__ dists, const float* __restrict__ cemb,
    const float* __restrict__ demb, const float* __restrict__ kt,
    const void* __restrict__ dbl, float* __restrict__ out)
{
    int b = blockIdx.x, tid = threadIdx.x;
    int w = tid >> 5, l = tid & 31;
    __shared__ __align__(16) float ks[DH];
    __shared__ int   cap_s[CC], dist_s[CC];
    __shared__ float u_s[CC];

    ks[tid] = kt[(size_t)b * DH + tid];
    if (tid < CC) {
        cap_s[tid]  = caps[b * CC + tid];
        dist_s[tid] = dists[b * CC + tid];
    }
    __syncthreads();

    int dval = g_dbl_is_u8 ? (int)((const unsigned char*)dbl)[b]
                           : ((const int*)dbl)[b];
    int need = dval ? 2 : 1;

    const float4* H4 = (const float4*)HtC + (size_t)b * (CC * DH / 4);
    const float4* k4 = (const float4*)ks;
    #pragma unroll
    for (int r = 0; r < 4; r++) {
        int c = w * 4 + r;
        const float4* hrow = H4 + c * 128;
        const float4* ce = (const float4*)cemb + cap_s[c]  * 128;
        const float4* de = (const float4*)demb + dist_s[c] * 128;
        float acc = 0.f;
        #pragma unroll
        for (int j = 0; j < 4; j++) {
            int i = j * 32 + l;
            float4 h = __ldcs(hrow + i);
            float4 a = ce[i], d = de[i], q = k4[i];
            acc += (h.x + a.x + d.x) * q.x + (h.y + a.y + d.y) * q.y
                 + (h.z + a.z + d.z) * q.z + (h.w + a.w + d.w) * q.w;
        }
        #pragma unroll
        for (int o = 16; o; o >>= 1) acc += __shfl_xor_sync(0xffffffffu, acc, o);
        if (l == 0) {
            float uu = acc * SCALE;
            if (cap_s[c] < need) uu = __int_as_float(0xff800000); // -inf
            u_s[c] = uu;
        }
    }
    __syncthreads();

    if (w == 0) {
        float x0 = u_s[l], x1 = u_s[l + 32];
        float m = fmaxf(x0, x1);
        #pragma unroll
        for (int o = 16; o; o >>= 1) m = fmaxf(m, __shfl_xor_sync(0xffffffffu, m, o));
        float e0 = expf(x0 - m), e1 = expf(x1 - m);
        float s = e0 + e1;
        #pragma unroll
        for (int o = 16; o; o >>= 1) s += __shfl_xor_sync(0xffffffffu, s, o);
        float inv = 1.f / s;
        out[(size_t)b * CC + l]      = e0 * inv;
        out[(size_t)b * CC + l + 32] = e1 * inv;
    }
}

extern "C" void kernel_launch(void* const* d_in, const int* in_sizes, int n_in,
                              void* d_out, int out_size) {
    const float* HtC   = (const float*)d_in[0];
    const int*   caps  = (const int*)  d_in[1];
    const int*   dists = (const int*)  d_in[2];
    const float* HX    = (const float*)d_in[3];
    const float* HS    = (const float*)d_in[4];
    const float* EQ    = (const float*)d_in[5];
    const void*  dbl   = d_in[6];
    const float* cemb  = (const float*)d_in[7];
    const float* demb  = (const float*)d_in[8];
    const float* Wq    = (const float*)d_in[9];
    const float* Wk    = (const float*)d_in[10];
    const float* Wv    = (const float*)d_in[11];
    float* out = (float*)d_out;

    bf16 *ctxh,*ctxl,*wqh,*wql,*wkh,*wkl,*wvh,*wvl,*w1h,*w1l,*m2h,*m2l,*gbh,*gbl;
    float *qt,*kt;
    cudaGetSymbolAddress((void**)&ctxh, g_ctx_h);  cudaGetSymbolAddress((void**)&ctxl, g_ctx_l);
    cudaGetSymbolAddress((void**)&wqh,  g_WqT_h);  cudaGetSymbolAddress((void**)&wql,  g_WqT_l);
    cudaGetSymbolAddress((void**)&wkh,  g_WkT_h);  cudaGetSymbolAddress((void**)&wkl,  g_WkT_l);
    cudaGetSymbolAddress((void**)&wvh,  g_WvT_h);  cudaGetSymbolAddress((void**)&wvl,  g_WvT_l);
    cudaGetSymbolAddress((void**)&w1h,  g_W1t_h);  cudaGetSymbolAddress((void**)&w1l,  g_W1t_l);
    cudaGetSymbolAddress((void**)&m2h,  g_M2t_h);  cudaGetSymbolAddress((void**)&m2l,  g_M2t_l);
    cudaGetSymbolAddress((void**)&gbh,  g_gbar_h); cudaGetSymbolAddress((void**)&gbl,  g_gbar_l);
    cudaGetSymbolAddress((void**)&qt,   g_qt);     cudaGetSymbolAddress((void**)&kt,   g_kt);

    cudaFuncSetAttribute(mma_gemm_kernel<0>, cudaFuncAttributeMaxDynamicSharedMemorySize, MG_SMEM);
    cudaFuncSetAttribute(mma_gemm_kernel<1>, cudaFuncAttributeMaxDynamicSharedMemorySize, MG_SMEM);
    const int F1_SMEM = CC * DH * 4;   // 128 KB dynamic
    cudaFuncSetAttribute(fused1_kernel, cudaFuncAttributeMaxDynamicSharedMemorySize, F1_SMEM);

    // 1) prep: weight transposes + dtype sniff (one launch)
    prep_kernel<<<1281, 256>>>(Wq, Wk, Wv, wqh, wql, wkh, wkl, wvh, wvl,
                               (const unsigned char*)dbl);
    // 2) pack + split context
    pack_split_kernel<<<(BB*384)/256, 256>>>((uint2*)ctxh, (uint2*)ctxl,
        (const float4*)HX, (const float4*)HS, (const float4*)EQ);
    // 3) W1t[d,i] = sum_e WkT[d,e]*WqT[i,e]   (M=512, N=1536, K=512)
    mma_gemm_kernel<1><<<dim3(K3/64, DH/128), 256, MG_SMEM>>>(
        nullptr, w1h, w1l, wkh, wkl, wqh, wql, K3, DH);
    // 4) M2t[d,e2] = sum_e WkT[d,e]*WvT[e2,e] (M=512, N=512, K=512)
    mma_gemm_kernel<1><<<dim3(DH/64, DH/128), 256, MG_SMEM>>>(
        nullptr, m2h, m2l, wkh, wkl, wvh, wvl, DH, DH);
    // 5) qt[b,d] = sum_i ctx[b,i]*W1t[d,i]    (M=2048, N=512, K=1536)
    mma_gemm_kernel<0><<<dim3(DH/64, BB/128), 256, MG_SMEM>>>(
        qt, nullptr, nullptr, ctxh, ctxl, w1h, w1l, DH, K3);
    // 6) logits/softmax/gbar (G cached in smem, single DRAM pass)
    fused1_kernel<<<BB, 512, F1_SMEM>>>(HtC, caps, dists, cemb, demb, qt, gbh, gbl);
    // 7) kt[b,d] = sum_e2 gbar[b,e2]*M2t[d,e2] (M=2048, N=512, K=512)
    mma_gemm_kernel<0><<<dim3(DH/64, BB/128), 256, MG_SMEM>>>(
        kt, nullptr, nullptr, gbh, gbl, m2h, m2l, DH, DH);
    // 8) u/mask/softmax -> out
    fused2_kernel<<<BB, 512>>>(HtC, caps, dists, cemb, demb, kt, dbl, out);
}

// round 6
// speedup vs baseline: 1.9731x; 1.0741x over previous
#include <cuda_runtime.h>
#include <cuda_bf16.h>
#include <math.h>
#include <stdint.h>

// Problem constants
#define BB   2048
#define CC   64
#define DH   512
#define K3   1536
#define NB2  (K3 + DH)                 // concat fold-B rows
#define SCALE 0.044194173824159216f   // 1/sqrt(512)

typedef unsigned long long u64;
typedef __nv_bfloat16 bf16;

// ---------------- scratch (static device globals) ----------------
__device__ bf16  g_ctx_h [BB * K3];
__device__ bf16  g_ctx_l [BB * K3];
__device__ bf16  g_WBT_h [NB2 * DH];  // rows 0..1535: WqT[i,e]; rows 1536..2047: WvT[e2,e]
__device__ bf16  g_WBT_l [NB2 * DH];
__device__ bf16  g_WkT_h [DH * DH];
__device__ bf16  g_WkT_l [DH * DH];
__device__ bf16  g_W1t_h [DH * K3];   // W1t[d,i] = sum_e WkT[d,e]*WqT[i,e]
__device__ bf16  g_W1t_l [DH * K3];
__device__ bf16  g_M2t_h [DH * DH];   // M2t[d,e2] = sum_e WkT[d,e]*WvT[e2,e]
__device__ bf16  g_M2t_l [DH * DH];
__device__ float g_qt    [BB * DH];
__device__ bf16  g_gbar_h[BB * DH];
__device__ bf16  g_gbar_l[BB * DH];
__device__ float g_kt    [BB * DH];
__device__ int   g_dbl_is_u8;

// ---------------- helpers ----------------
__device__ __forceinline__ uint32_t smem_u32(const void* p) {
    uint32_t a;
    asm("{ .reg .u64 t; cvta.to.shared.u64 t, %1; cvt.u32.u64 %0, t; }" : "=r"(a) : "l"(p));
    return a;
}
__device__ __forceinline__ void cp_async16(uint32_t dst, const void* src) {
    asm volatile("cp.async.cg.shared.global [%0], [%1], 16;" :: "r"(dst), "l"(src) : "memory");
}
__device__ __forceinline__ void cp_commit() {
    asm volatile("cp.async.commit_group;" ::: "memory");
}
__device__ __forceinline__ void split_bf16(float f, bf16& h, bf16& l) {
    h = __float2bfloat16_rn(f);
    l = __float2bfloat16_rn(f - __bfloat162float(h));
}
__device__ __forceinline__ void mma_bf16(float* c, const uint32_t* a, const uint32_t* b) {
    asm volatile(
        "mma.sync.aligned.m16n8k16.row.col.f32.bf16.bf16.f32 "
        "{%0,%1,%2,%3}, {%4,%5,%6,%7}, {%8,%9}, {%0,%1,%2,%3};"
        : "+f"(c[0]), "+f"(c[1]), "+f"(c[2]), "+f"(c[3])
        : "r"(a[0]), "r"(a[1]), "r"(a[2]), "r"(a[3]), "r"(b[0]), "r"(b[1]));
}
__device__ __forceinline__ void ldmx4(uint32_t* r, uint32_t saddr) {
    asm volatile("ldmatrix.sync.aligned.m8n8.x4.shared.b16 {%0,%1,%2,%3}, [%4];"
        : "=r"(r[0]), "=r"(r[1]), "=r"(r[2]), "=r"(r[3]) : "r"(saddr));
}

// ---------------- prep: weight transposes+splits (concat B), dtype sniff ----------------
// blocks 0..767: Wq -> WBT rows 0..1535; 768..1023: Wk -> WkT; 1024..1279: Wv -> WBT rows 1536+; 1280: sniff.
__global__ void prep_kernel(const float* __restrict__ Wq,
                            const float* __restrict__ Wk,
                            const float* __restrict__ Wv,
                            bf16* __restrict__ wbh, bf16* __restrict__ wbl,
                            bf16* __restrict__ wkh, bf16* __restrict__ wkl,
                            const unsigned char* __restrict__ dblp) {
    int bid = blockIdx.x;
    int tx = threadIdx.x & 31, ty = threadIdx.x >> 5;   // 32 x 8
    if (bid == 1280) {
        __shared__ int any;
        if (threadIdx.x == 0) any = 0;
        __syncthreads();
        int found = 0;
        for (int i = threadIdx.x; i < 2048; i += 256)
            if ((i & 3) && dblp[i]) found = 1;
        if (found) any = 1;
        __syncthreads();
        if (threadIdx.x == 0) g_dbl_is_u8 = any;
        return;
    }
    const float* in; bf16 *oh, *ol; int Cn, bx, by, roff;
    if (bid < 768)       { in = Wq; oh = wbh; ol = wbl; Cn = K3; bx = bid % 48;          by = bid / 48;         roff = 0; }
    else if (bid < 1024) { in = Wk; oh = wkh; ol = wkl; Cn = DH; bx = (bid - 768) & 15;  by = (bid - 768) >> 4; roff = 0; }
    else                 { in = Wv; oh = wbh; ol = wbl; Cn = DH; bx = (bid - 1024) & 15; by = (bid - 1024) >> 4; roff = K3; }
    __shared__ float t[32][33];
    int i0 = bx * 32, e0 = by * 32;
    #pragma unroll
    for (int j = 0; j < 32; j += 8)
        t[ty + j][tx] = in[(size_t)(e0 + ty + j) * Cn + i0 + tx];
    __syncthreads();
    #pragma unroll
    for (int j = 0; j < 32; j += 8) {
        float f = t[tx][ty + j];
        bf16 h, l; split_bf16(f, h, l);
        size_t o = (size_t)(roff + i0 + ty + j) * DH + e0 + tx;
        oh[o] = h; ol[o] = l;
    }
}

// ---------------- pack context + split to bf16 hi/lo ----------------
__global__ void pack_split_kernel(uint2* __restrict__ ch, uint2* __restrict__ cl,
                                  const float4* __restrict__ hx,
                                  const float4* __restrict__ hs,
                                  const float4* __restrict__ eq) {
    int idx = blockIdx.x * blockDim.x + threadIdx.x;   // BB*384 float4s
    int b = idx / 384;
    int r = idx - b * 384;
    float4 v;
    if (r < 128)       v = hx[b * 128 + r];
    else if (r < 256)  v = hs[b * 128 + (r - 128)];
    else               v = eq[b * 128 + (r - 256)];
    bf16 h0,l0,h1,l1,h2,l2,h3,l3;
    split_bf16(v.x,h0,l0); split_bf16(v.y,h1,l1);
    split_bf16(v.z,h2,l2); split_bf16(v.w,h3,l3);
    __nv_bfloat162 H01 = {h0,h1}, H23 = {h2,h3}, L01 = {l0,l1}, L23 = {l2,l3};
    ch[idx] = make_uint2(*(uint32_t*)&H01, *(uint32_t*)&H23);
    cl[idx] = make_uint2(*(uint32_t*)&L01, *(uint32_t*)&L23);
}

// ---------------- mma.sync GEMM: D[m,n] = sum_k A[m,k]*B[n,k] ----------------
// bf16 hi/lo operands, K-major; 3-term split accumulated in fp32.
// CTA 128x64, BK=32, 256 threads (4M x 2N warps), 3-stage cp.async, ldmatrix loads.
// MODE 0: fp32 out [*,N]; MODE 2: fold, split out routed to W1t (col<K3) / M2t.
#define MG_AH   0
#define MG_AL   10240
#define MG_BH   20480
#define MG_BL   25600
#define MG_STG  30720
#define MG_SMEM (3 * MG_STG)

template<int MODE>
__global__ void __launch_bounds__(256, 1) mma_gemm_kernel(
    float* __restrict__ outf,
    bf16* __restrict__ o1h, bf16* __restrict__ o1l,
    bf16* __restrict__ o2h, bf16* __restrict__ o2l,
    const bf16* __restrict__ Ah, const bf16* __restrict__ Al,
    const bf16* __restrict__ Bh, const bf16* __restrict__ Bl,
    int N, int K)
{
    extern __shared__ char dsm[];
    uint32_t sb0 = smem_u32(dsm);

    int tid = threadIdx.x;
    int lane = tid & 31, wid = tid >> 5;
    int wm = wid & 3, wn = wid >> 2;          // 4 M-warps x 2 N-warps
    int gid = lane >> 2, tid4 = lane & 3;
    int lr = lane & 7, sel = lane >> 3;
    int bm = blockIdx.y * 128, bn = blockIdx.x * 64;
    int KB = K >> 5;

    // ldmatrix lane address components
    uint32_t a_row    = (uint32_t)(wm * 32 + lr + (sel & 1) * 8);
    uint32_t a_coloff = (uint32_t)((sel >> 1) * 8);
    uint32_t b_row    = (uint32_t)(wn * 32 + lr + (sel >> 1) * 8);
    uint32_t b_coloff = (uint32_t)((sel & 1) * 8);

    float C[2][4][4];
    #pragma unroll
    for (int t = 0; t < 2; t++)
        #pragma unroll
        for (int j = 0; j < 4; j++)
            #pragma unroll
            for (int q = 0; q < 4; q++) C[t][j][q] = 0.f;

    auto load_stage = [&](int kb, int s) {
        uint32_t sb = sb0 + s * MG_STG;
        int ko = kb * 32;
        #pragma unroll
        for (int i = 0; i < 6; i++) {
            int v = tid + i * 256;
            if (v < 512) {
                int r = v >> 2, c = v & 3;
                cp_async16(sb + MG_AH + r * 80 + c * 16,
                           Ah + (size_t)(bm + r) * K + ko + c * 8);
            } else if (v < 1024) {
                int u = v - 512; int r = u >> 2, c = u & 3;
                cp_async16(sb + MG_AL + r * 80 + c * 16,
                           Al + (size_t)(bm + r) * K + ko + c * 8);
            } else if (v < 1280) {
                int u = v - 1024; int r = u >> 2, c = u & 3;
                cp_async16(sb + MG_BH + r * 80 + c * 16,
                           Bh + (size_t)(bn + r) * K + ko + c * 8);
            } else {
                int u = v - 1280; int r = u >> 2, c = u & 3;
                cp_async16(sb + MG_BL + r * 80 + c * 16,
                           Bl + (size_t)(bn + r) * K + ko + c * 8);
            }
        }
        cp_commit();
    };

    load_stage(0, 0);
    if (KB > 1) load_stage(1, 1);

    for (int kb = 0; kb < KB; kb++) {
        if (kb + 2 < KB) {
            load_stage(kb + 2, (kb + 2) % 3);
            asm volatile("cp.async.wait_group 2;" ::: "memory");
        } else if (kb + 1 < KB) {
            asm volatile("cp.async.wait_group 1;" ::: "memory");
        } else {
            asm volatile("cp.async.wait_group 0;" ::: "memory");
        }
        __syncthreads();

        uint32_t st = sb0 + (kb % 3) * MG_STG;
        #pragma unroll
        for (int step = 0; step < 2; step++) {
            int kbase = step * 16;
            uint32_t ah[2][4], al[2][4], bh[8], bl[8];
            #pragma unroll
            for (int t = 0; t < 2; t++) {
                uint32_t aa = st + MG_AH + (a_row + t * 16) * 80 + (kbase + a_coloff) * 2;
                ldmx4(ah[t], aa);
                ldmx4(al[t], aa + (MG_AL - MG_AH));
            }
            #pragma unroll
            for (int jp = 0; jp < 2; jp++) {
                uint32_t ba = st + MG_BH + (b_row + jp * 16) * 80 + (kbase + b_coloff) * 2;
                ldmx4(&bh[jp * 4], ba);
                ldmx4(&bl[jp * 4], ba + (MG_BL - MG_BH));
            }
            #pragma unroll
            for (int t = 0; t < 2; t++)
                #pragma unroll
                for (int j = 0; j < 4; j++) {
                    mma_bf16(C[t][j], ah[t], &bh[j * 2]);
                    mma_bf16(C[t][j], ah[t], &bl[j * 2]);
                    mma_bf16(C[t][j], al[t], &bh[j * 2]);
                }
        }
        __syncthreads();
    }

    // epilogue
    bf16 *ph = o1h, *pl = o1l;
    int nstride = K3, coff = 0;
    if (MODE == 2 && bn >= K3) { ph = o2h; pl = o2l; nstride = DH; coff = K3; }
    #pragma unroll
    for (int t = 0; t < 2; t++) {
        int m0 = bm + wm * 32 + t * 16 + gid;
        #pragma unroll
        for (int j = 0; j < 4; j++) {
            int col = bn + wn * 32 + j * 8 + tid4 * 2;
            if (MODE == 2) {
                bf16 h0,l0,h1,l1;
                split_bf16(C[t][j][0], h0, l0); split_bf16(C[t][j][1], h1, l1);
                __nv_bfloat162 H = {h0,h1}, L = {l0,l1};
                *(uint32_t*)(ph + (size_t)m0 * nstride + col - coff) = *(uint32_t*)&H;
                *(uint32_t*)(pl + (size_t)m0 * nstride + col - coff) = *(uint32_t*)&L;
                split_bf16(C[t][j][2], h0, l0); split_bf16(C[t][j][3], h1, l1);
                __nv_bfloat162 H2 = {h0,h1}, L2 = {l0,l1};
                *(uint32_t*)(ph + (size_t)(m0 + 8) * nstride + col - coff) = *(uint32_t*)&H2;
                *(uint32_t*)(pl + (size_t)(m0 + 8) * nstride + col - coff) = *(uint32_t*)&L2;
            } else {
                *(float2*)(outf + (size_t)m0 * N + col)       = make_float2(C[t][j][0], C[t][j][1]);
                *(float2*)(outf + (size_t)(m0 + 8) * N + col) = make_float2(C[t][j][2], C[t][j][3]);
            }
        }
    }
}

// ---------------- fused pass 1: logits -> softmax -> gbar(split) ----------------
// G tile (64x512 fp32 = 128 KB) cached in dynamic smem: Ht_C read ONCE from DRAM.
__global__ void __launch_bounds__(512, 1) fused1_kernel(
    const float* __restrict__ HtC, const int* __restrict__ caps,
    const int* __restrict__ dists, const float* __restrict__ cemb,
    const float* __restrict__ demb, const float* __restrict__ qt,
    bf16* __restrict__ gbh, bf16* __restrict__ gbl)
{
    extern __shared__ float4 gsm4[];   // [CC * 128] float4 = 128 KB
    int b = blockIdx.x, tid = threadIdx.x;
    int w = tid >> 5, l = tid & 31;
    __shared__ __align__(16) float qs[DH];
    __shared__ int   cap_s[CC], dist_s[CC];
    __shared__ float logit_s[CC], attn_s[CC];

    qs[tid] = qt[(size_t)b * DH + tid];
    if (tid < CC) {
        cap_s[tid]  = caps[b * CC + tid];
        dist_s[tid] = dists[b * CC + tid];
    }
    __syncthreads();

    const float4* H4 = (const float4*)HtC + (size_t)b * (CC * DH / 4);
    const float4* q4 = (const float4*)qs;
    #pragma unroll
    for (int r = 0; r < 4; r++) {
        int c = w * 4 + r;
        const float4* hrow = H4 + c * 128;
        const float4* ce = (const float4*)cemb + cap_s[c]  * 128;
        const float4* de = (const float4*)demb + dist_s[c] * 128;
        float acc = 0.f;
        #pragma unroll
        for (int j = 0; j < 4; j++) {
            int i = j * 32 + l;
            float4 h = __ldcs(hrow + i);
            float4 a = ce[i], d = de[i], q = q4[i];
            float4 g = make_float4(h.x + a.x + d.x, h.y + a.y + d.y,
                                   h.z + a.z + d.z, h.w + a.w + d.w);
            gsm4[c * 128 + i] = g;
            acc += g.x * q.x + g.y * q.y + g.z * q.z + g.w * q.w;
        }
        #pragma unroll
        for (int o = 16; o; o >>= 1) acc += __shfl_xor_sync(0xffffffffu, acc, o);
        if (l == 0) logit_s[c] = acc * SCALE;
    }
    __syncthreads();

    if (w == 0) {
        float x0 = logit_s[l], x1 = logit_s[l + 32];
        float m = fmaxf(x0, x1);
        #pragma unroll
        for (int o = 16; o; o >>= 1) m = fmaxf(m, __shfl_xor_sync(0xffffffffu, m, o));
        float e0 = expf(x0 - m), e1 = expf(x1 - m);
        float s = e0 + e1;
        #pragma unroll
        for (int o = 16; o; o >>= 1) s += __shfl_xor_sync(0xffffffffu, s, o);
        float inv = 1.f / s;
        attn_s[l] = e0 * inv; attn_s[l + 32] = e1 * inv;
    }
    __syncthreads();

    // gbar[d] = sum_c attn[c] * G[c][d]  (G from smem)
    const float* gs = (const float*)gsm4;
    float acc = 0.f;
    #pragma unroll 16
    for (int c = 0; c < CC; c++)
        acc = fmaf(attn_s[c], gs[c * DH + tid], acc);
    bf16 h, lo; split_bf16(acc, h, lo);
    gbh[(size_t)b * DH + tid] = h;
    gbl[(size_t)b * DH + tid] = lo;
}

// ---------------- fused pass 2: u -> mask -> softmax -> out ----------------
__global__ void __launch_bounds__(512) fused2_kernel(
    const float* __restrict__ HtC, const int* __restrict__ caps,
    const int* __restrict__ dists, const float* __restrict__ cemb,
    const float* __restrict__ demb, const float* __restrict__ kt,
    const void* __restrict__ dbl, float* __restrict__ out)
{
    int b = blockIdx.x, tid = threadIdx.x;
    int w = tid >> 5, l = tid & 31;
    __shared__ __align__(16) float ks[DH];
    __shared__ int   cap_s[CC], dist_s[CC];
    __shared__ float u_s[CC];

    ks[tid] = kt[(size_t)b * DH + tid];
    if (tid < CC) {
        cap_s[tid]  = caps[b * CC + tid];
        dist_s[tid] = dists[b * CC + tid];
    }
    __syncthreads();

    int dval = g_dbl_is_u8 ? (int)((const unsigned char*)dbl)[b]
                           : ((const int*)dbl)[b];
    int need = dval ? 2 : 1;

    const float4* H4 = (const float4*)HtC + (size_t)b * (CC * DH / 4);
    const float4* k4 = (const float4*)ks;
    #pragma unroll
    for (int r = 0; r < 4; r++) {
        int c = w * 4 + r;
        const float4* hrow = H4 + c * 128;
        const float4* ce = (const float4*)cemb + cap_s[c]  * 128;
        const float4* de = (const float4*)demb + dist_s[c] * 128;
        float acc = 0.f;
        #pragma unroll
        for (int j = 0; j < 4; j++) {
            int i = j * 32 + l;
            float4 h = __ldcs(hrow + i);
            float4 a = ce[i], d = de[i], q = k4[i];
            acc += (h.x + a.x + d.x) * q.x + (h.y + a.y + d.y) * q.y
                 + (h.z + a.z + d.z) * q.z + (h.w + a.w + d.w) * q.w;
        }
        #pragma unroll
        for (int o = 16; o; o >>= 1) acc += __shfl_xor_sync(0xffffffffu, acc, o);
        if (l == 0) {
            float uu = acc * SCALE;
            if (cap_s[c] < need) uu = __int_as_float(0xff800000); // -inf
            u_s[c] = uu;
        }
    }
    __syncthreads();

    if (w == 0) {
        float x0 = u_s[l], x1 = u_s[l + 32];
        float m = fmaxf(x0, x1);
        #pragma unroll
        for (int o = 16; o; o >>= 1) m = fmaxf(m, __shfl_xor_sync(0xffffffffu, m, o));
        float e0 = expf(x0 - m), e1 = expf(x1 - m);
        float s = e0 + e1;
        #pragma unroll
        for (int o = 16; o; o >>= 1) s += __shfl_xor_sync(0xffffffffu, s, o);
        float inv = 1.f / s;
        out[(size_t)b * CC + l]      = e0 * inv;
        out[(size_t)b * CC + l + 32] = e1 * inv;
    }
}

extern "C" void kernel_launch(void* const* d_in, const int* in_sizes, int n_in,
                              void* d_out, int out_size) {
    const float* HtC   = (const float*)d_in[0];
    const int*   caps  = (const int*)  d_in[1];
    const int*   dists = (const int*)  d_in[2];
    const float* HX    = (const float*)d_in[3];
    const float* HS    = (const float*)d_in[4];
    const float* EQ    = (const float*)d_in[5];
    const void*  dbl   = d_in[6];
    const float* cemb  = (const float*)d_in[7];
    const float* demb  = (const float*)d_in[8];
    const float* Wq    = (const float*)d_in[9];
    const float* Wk    = (const float*)d_in[10];
    const float* Wv    = (const float*)d_in[11];
    float* out = (float*)d_out;

    bf16 *ctxh,*ctxl,*wbh,*wbl,*wkh,*wkl,*w1h,*w1l,*m2h,*m2l,*gbh,*gbl;
    float *qt,*kt;
    cudaGetSymbolAddress((void**)&ctxh, g_ctx_h);  cudaGetSymbolAddress((void**)&ctxl, g_ctx_l);
    cudaGetSymbolAddress((void**)&wbh,  g_WBT_h);  cudaGetSymbolAddress((void**)&wbl,  g_WBT_l);
    cudaGetSymbolAddress((void**)&wkh,  g_WkT_h);  cudaGetSymbolAddress((void**)&wkl,  g_WkT_l);
    cudaGetSymbolAddress((void**)&w1h,  g_W1t_h);  cudaGetSymbolAddress((void**)&w1l,  g_W1t_l);
    cudaGetSymbolAddress((void**)&m2h,  g_M2t_h);  cudaGetSymbolAddress((void**)&m2l,  g_M2t_l);
    cudaGetSymbolAddress((void**)&gbh,  g_gbar_h); cudaGetSymbolAddress((void**)&gbl,  g_gbar_l);
    cudaGetSymbolAddress((void**)&qt,   g_qt);     cudaGetSymbolAddress((void**)&kt,   g_kt);

    cudaFuncSetAttribute(mma_gemm_kernel<0>, cudaFuncAttributeMaxDynamicSharedMemorySize, MG_SMEM);
    cudaFuncSetAttribute(mma_gemm_kernel<2>, cudaFuncAttributeMaxDynamicSharedMemorySize, MG_SMEM);
    const int F1_SMEM = CC * DH * 4;   // 128 KB dynamic
    cudaFuncSetAttribute(fused1_kernel, cudaFuncAttributeMaxDynamicSharedMemorySize, F1_SMEM);

    // 1) prep: weight transposes (B concat) + dtype sniff
    prep_kernel<<<1281, 256>>>(Wq, Wk, Wv, wbh, wbl, wkh, wkl,
                               (const unsigned char*)dbl);
    // 2) pack + split context
    pack_split_kernel<<<(BB*384)/256, 256>>>((uint2*)ctxh, (uint2*)ctxl,
        (const float4*)HX, (const float4*)HS, (const float4*)EQ);
    // 3) fold (merged): D[d, 0..2047] = sum_e WkT[d,e]*WBT[n,e] -> W1t | M2t
    mma_gemm_kernel<2><<<dim3(NB2/64, DH/128), 256, MG_SMEM>>>(
        nullptr, w1h, w1l, m2h, m2l, wkh, wkl, wbh, wbl, NB2, DH);
    // 4) qt[b,d] = sum_i ctx[b,i]*W1t[d,i]    (M=2048, N=512, K=1536)
    mma_gemm_kernel<0><<<dim3(DH/64, BB/128), 256, MG_SMEM>>>(
        qt, nullptr, nullptr, nullptr, nullptr, ctxh, ctxl, w1h, w1l, DH, K3);
    // 5) logits/softmax/gbar (G cached in smem, single DRAM pass)
    fused1_kernel<<<BB, 512, F1_SMEM>>>(HtC, caps, dists, cemb, demb, qt, gbh, gbl);
    // 6) kt[b,d] = sum_e2 gbar[b,e2]*M2t[d,e2] (M=2048, N=512, K=512)
    mma_gemm_kernel<0><<<dim3(DH/64, BB/128), 256, MG_SMEM>>>(
        kt, nullptr, nullptr, nullptr, nullptr, gbh, gbl, m2h, m2l, DH, DH);
    // 7) u/mask/softmax -> out
    fused2_kernel<<<BB, 512>>>(HtC, caps, dists, cemb, demb, kt, dbl, out);
}